// round 7
// baseline (speedup 1.0000x reference)
#include <cuda_runtime.h>
#include <cuda_bf16.h>
#include <cstdint>

// out[64,11008] = x[64,4096] @ (Wq*scale)^T + bias
// v4: split-K(8); 4 warps/CTA, warp = M64 x N32 (halves A-smem crossbar traffic
//     per W byte); BKR=32 with 4-deep cp.async circular buffer, 1 sync/stage.

#define M_DIM 64
#define K_DIM 4096
#define N_DIM 11008

#define SPLITS 8
#define KSR    512          // real k per split
#define BKR    32           // real k per stage
#define NST    (KSR / BKR)  // 16 stages per CTA
#define BKE    64           // effective k per stage (hi/lo)
#define SA     72           // smem row stride in bf16 elems (64 + 8 pad)
#define ABUF_B (M_DIM * SA * 2)   // bytes per A stage buffer (9216)
#define NBUF   4
#define BN     128          // CTA n-tile
#define THREADS 128

__device__ __align__(16) __nv_bfloat16 g_Axl[M_DIM * 8192];          // 1 MB
__device__ float g_part[SPLITS * M_DIM * N_DIM];                     // 22.5 MB

__device__ __forceinline__ unsigned pack_bf2(__nv_bfloat16 a, __nv_bfloat16 b) {
    return (unsigned)__bfloat16_as_ushort(a) | ((unsigned)__bfloat16_as_ushort(b) << 16);
}

// ---------------------------------------------------------------------------
// Kernel 1: x[64,4096] f32 -> g_Axl[64,8192] bf16, permuted hi/lo layout.
// Per 16-real-k block j: 32 keff slots; slot(sp,b,qp,e) = sp*16 + b*8 + 2qp + e
//   real k = 16j + 4qp + 2sp + e ; b=0 -> hi(x), b=1 -> lo(x)
// ---------------------------------------------------------------------------
__global__ void convx_kernel(const float* __restrict__ x) {
    int t = blockIdx.x * blockDim.x + threadIdx.x;   // 0..16383
    int m  = t >> 8;          // 0..63
    int st = (t >> 2) & 63;   // 64-real-k super-stage
    int j  = t & 3;           // 16-real-k block

    float fx[16];
    const float4* src = (const float4*)(x + m * K_DIM + st * 64 + j * 16);
    #pragma unroll
    for (int q = 0; q < 4; ++q) ((float4*)fx)[q] = src[q];

    unsigned u[16];
    #pragma unroll
    for (int sp = 0; sp < 2; ++sp) {
        #pragma unroll
        for (int qp = 0; qp < 4; ++qp) {
            int kl = 4 * qp + 2 * sp;
            float a = fx[kl], c = fx[kl + 1];
            __nv_bfloat16 ha = __float2bfloat16_rn(a);
            __nv_bfloat16 hc = __float2bfloat16_rn(c);
            float la = a - __bfloat162float(ha);
            float lc = c - __bfloat162float(hc);
            u[sp * 8 + qp]     = pack_bf2(ha, hc);
            u[sp * 8 + 4 + qp] = pack_bf2(__float2bfloat16_rn(la), __float2bfloat16_rn(lc));
        }
    }
    uint4* dst = (uint4*)(g_Axl + m * 8192 + st * 128 + j * 32);
    #pragma unroll
    for (int q = 0; q < 4; ++q) dst[q] = ((const uint4*)u)[q];
}

// ---------------------------------------------------------------------------
// Kernel 2: split-K GEMM.  CTA: 4 warps, warp = M64 x N32.  grid (86, 8).
// ---------------------------------------------------------------------------
#define MMA16816(d, a0, a1, a2, a3, b)                                          \
    asm volatile(                                                               \
        "mma.sync.aligned.m16n8k16.row.col.f32.bf16.bf16.f32 "                  \
        "{%0,%1,%2,%3}, {%4,%5,%6,%7}, {%8,%9}, {%0,%1,%2,%3};\n"               \
        : "+f"(d[0]), "+f"(d[1]), "+f"(d[2]), "+f"(d[3])                        \
        : "r"(a0), "r"(a1), "r"(a2), "r"(a3), "r"(b), "r"(b))

// A stage copy: 64 rows x 64 keff bf16 (128B/row), 128 thr x 4 x 16B.
__device__ __forceinline__ void issue_a(uint32_t sb, const __nv_bfloat16* agsrc,
                                        int kt, int buf) {
    #pragma unroll
    for (int j = 0; j < 4; ++j) {
        uint32_t d = sb + buf * ABUF_B + j * (16 * SA * 2);
        const void* s = agsrc + kt * BKE + (size_t)j * 16 * 8192;
        asm volatile("cp.async.cg.shared.global [%0], [%1], 16;\n"
                     :: "r"(d), "l"(s));
    }
}

__global__ __launch_bounds__(THREADS, 4)
void qgemm_kernel(const int* __restrict__ wq, float* __restrict__ part) {
    __shared__ __align__(16) __nv_bfloat16 As[NBUF][M_DIM * SA];

    const int tid  = threadIdx.x;
    const int lane = tid & 31;
    const int wid  = tid >> 5;
    const int qp   = lane & 3;
    const int g    = lane >> 2;
    const int bn0   = blockIdx.x * BN;
    const int split = blockIdx.y;

    uint32_t sb;
    { void* p = (void*)As;
      asm("{.reg .u64 t; cvta.to.shared.u64 t, %1; cvt.u32.u64 %0, t;}"
          : "=r"(sb) : "l"(p)); }

    // ---- A cp.async mapping: 512 chunks of 16B, 4 per thread
    const int acol = tid & 7;             // 16B chunk within 128B row
    const int arow = tid >> 3;            // base row (16 rows), +16 per j
    const __nv_bfloat16* agsrc =
        g_Axl + (size_t)arow * 8192 + split * (KSR * 2) + acol * 8;
    const uint32_t adst0 = sb + (uint32_t)((arow * SA + acol * 8) * 2);

    // ---- B pointers: frag fn row = bn0 + wid*32 + fn*8 + g
    const int* wg[4];
    #pragma unroll
    for (int fn = 0; fn < 4; ++fn)
        wg[fn] = wq + (size_t)(bn0 + wid * 32 + fn * 8 + g) * K_DIM
                    + split * KSR + 4 * qp;

    int4 Bn[4][2];

    // ---- prologue: A stages 0..2, B stage 0
    issue_a(adst0, agsrc, 0, 0);
    asm volatile("cp.async.commit_group;\n");
    issue_a(adst0, agsrc, 1, 1);
    asm volatile("cp.async.commit_group;\n");
    issue_a(adst0, agsrc, 2, 2);
    asm volatile("cp.async.commit_group;\n");
    #pragma unroll
    for (int fn = 0; fn < 4; ++fn) {
        Bn[fn][0] = *(const int4*)(wg[fn]);
        Bn[fn][1] = *(const int4*)(wg[fn] + 16);
    }

    float acc[4][4][4];
    #pragma unroll
    for (int a = 0; a < 4; ++a)
        #pragma unroll
        for (int b = 0; b < 4; ++b)
            #pragma unroll
            for (int c = 0; c < 4; ++c) acc[a][b][c] = 0.0f;

    const uint32_t aptr = sb + (uint32_t)(((lane & 15) * SA + (lane >> 4) * 8) * 2);

    for (int kt = 0; kt < NST; ++kt) {
        // stage kt data ready for this thread; sync makes it ready for all and
        // confirms everyone is done reading the buffer we are about to refill.
        asm volatile("cp.async.wait_group 3;\n");
        __syncthreads();
        if (kt + 3 < NST) issue_a(adst0, agsrc, kt + 3, (kt + 3) & 3);
        asm volatile("cp.async.commit_group;\n");

        const uint32_t abuf = aptr + (kt & 3) * ABUF_B;
        const bool pf = (kt + 1 < NST);

        #pragma unroll
        for (int s = 0; s < 4; ++s) {
            const int j = s >> 1;
            unsigned bb[4];
            #pragma unroll
            for (int fn = 0; fn < 4; ++fn) {
                int vx, vy;
                if ((s & 1) == 0) { vx = Bn[fn][j].x; vy = Bn[fn][j].y; }
                else              { vx = Bn[fn][j].z; vy = Bn[fn][j].w; }
                float f0 = (float)vx, f1 = (float)vy;
                asm("cvt.rn.bf16x2.f32 %0, %1, %2;" : "=r"(bb[fn]) : "f"(f1), "f"(f0));
            }
            // refill Bn[*][j] for next stage once its last user (odd s) is done
            if ((s & 1) == 1 && pf) {
                #pragma unroll
                for (int fn = 0; fn < 4; ++fn)
                    Bn[fn][j] = *(const int4*)(wg[fn] + (kt + 1) * BKR + 16 * j);
            }
            #pragma unroll
            for (int fm = 0; fm < 4; ++fm) {
                unsigned a0, a1, a2, a3;
                asm volatile(
                    "ldmatrix.sync.aligned.m8n8.x4.shared.b16 {%0,%1,%2,%3}, [%4];\n"
                    : "=r"(a0), "=r"(a1), "=r"(a2), "=r"(a3)
                    : "r"(abuf + fm * (16 * SA * 2) + s * 32));
                MMA16816(acc[fm][0], a0, a1, a2, a3, bb[0]);
                MMA16816(acc[fm][1], a0, a1, a2, a3, bb[1]);
                MMA16816(acc[fm][2], a0, a1, a2, a3, bb[2]);
                MMA16816(acc[fm][3], a0, a1, a2, a3, bb[3]);
            }
        }
    }

    // ---- epilogue: partials to scratch
    float* P = part + (size_t)split * (M_DIM * N_DIM);
    #pragma unroll
    for (int fm = 0; fm < 4; ++fm) {
        const int m0 = fm * 16 + g;
        #pragma unroll
        for (int fn = 0; fn < 4; ++fn) {
            const int n = bn0 + wid * 32 + fn * 8 + 2 * qp;
            *(float2*)(P + (size_t)m0 * N_DIM + n) =
                make_float2(acc[fm][fn][0], acc[fm][fn][1]);
            *(float2*)(P + (size_t)(m0 + 8) * N_DIM + n) =
                make_float2(acc[fm][fn][2], acc[fm][fn][3]);
        }
    }
}

// ---------------------------------------------------------------------------
// Kernel 3: out = scale * (sum of partials) + bias     (float4 vectorized)
// ---------------------------------------------------------------------------
__global__ void reduce_kernel(const float* __restrict__ wscale,
                              const float* __restrict__ bias,
                              float* __restrict__ out) {
    const int TOT4 = M_DIM * N_DIM / 4;
    int i = blockIdx.x * blockDim.x + threadIdx.x;
    if (i >= TOT4) return;
    const float4* P = (const float4*)g_part;
    float sx = 0.0f, sy = 0.0f, sz = 0.0f, sw = 0.0f;
    #pragma unroll
    for (int s = 0; s < SPLITS; ++s) {
        float4 v = P[i + (size_t)s * TOT4];
        sx += v.x; sy += v.y; sz += v.z; sw += v.w;
    }
    const float sc = wscale[0];
    int n = (4 * i) % N_DIM;
    float4 bs = *(const float4*)(bias + n);
    ((float4*)out)[i] = make_float4(sc * sx + bs.x, sc * sy + bs.y,
                                    sc * sz + bs.z, sc * sw + bs.w);
}

extern "C" void kernel_launch(void* const* d_in, const int* in_sizes, int n_in,
                              void* d_out, int out_size) {
    const float* x      = (const float*)d_in[0];
    const int*   wq     = (const int*)  d_in[1];
    const float* wscale = (const float*)d_in[2];
    const float* bias   = (const float*)d_in[3];
    float*       out    = (float*)d_out;

    float* part;
    cudaGetSymbolAddress((void**)&part, g_part);

    convx_kernel<<<128, 128>>>(x);
    qgemm_kernel<<<dim3(N_DIM / BN, SPLITS), THREADS>>>(wq, part);
    reduce_kernel<<<(M_DIM * N_DIM / 4 + 255) / 256, 256>>>(wscale, bias, out);
}